// round 7
// baseline (speedup 1.0000x reference)
#include <cuda_runtime.h>
#include <cuda_bf16.h>
#include <math.h>
#include <stdint.h>

#define MTOK 8192
#define DDIM 1024
#define HDIM 4096
#define NCB  8
#define KCB  256

__device__ __nv_bfloat16 g_xhi [(size_t)MTOK * DDIM];
__device__ __nv_bfloat16 g_xlo [(size_t)MTOK * DDIM];
__device__ __nv_bfloat16 g_w1hi[(size_t)HDIM * DDIM];
__device__ __nv_bfloat16 g_w1lo[(size_t)HDIM * DDIM];
__device__ __nv_bfloat16 g_w2hi[(size_t)DDIM * HDIM];
__device__ __nv_bfloat16 g_w2lo[(size_t)DDIM * HDIM];
__device__ __nv_bfloat16 g_hhi [(size_t)MTOK * HDIM];
__device__ __nv_bfloat16 g_hlo [(size_t)MTOK * HDIM];

// ---------------------------------------------------------------------------
__device__ __forceinline__ uint32_t smem_u32(const void* p) {
    uint32_t a;
    asm("{ .reg .u64 t; cvta.to.shared.u64 t, %1; cvt.u32.u64 %0, t; }"
        : "=r"(a) : "l"(p));
    return a;
}

#define CP_ASYNC16(dst, src) \
    asm volatile("cp.async.cg.shared.global [%0], [%1], 16;" \
        :: "r"(dst), "l"(src) : "memory")
#define CP_COMMIT() asm volatile("cp.async.commit_group;" ::: "memory")
#define CP_WAIT1()  asm volatile("cp.async.wait_group 1;"  ::: "memory")

#define LDSM_X4(r0, r1, r2, r3, a) \
    asm volatile("ldmatrix.sync.aligned.m8n8.x4.shared.b16 {%0,%1,%2,%3}, [%4];" \
        : "=r"(r0), "=r"(r1), "=r"(r2), "=r"(r3) : "r"(a))

#define MMA_BF16(c, a, b0, b1) \
    asm volatile("mma.sync.aligned.m16n8k16.row.col.f32.bf16.bf16.f32 " \
        "{%0,%1,%2,%3}, {%4,%5,%6,%7}, {%8,%9}, {%0,%1,%2,%3};" \
        : "+f"((c)[0]), "+f"((c)[1]), "+f"((c)[2]), "+f"((c)[3]) \
        : "r"((a)[0]), "r"((a)[1]), "r"((a)[2]), "r"((a)[3]), "r"(b0), "r"(b1))

// ---------------------------------------------------------------------------
// Pre-pass kernels
// ---------------------------------------------------------------------------
__device__ __forceinline__ void split4(float4 v, uint32_t& hi0, uint32_t& hi1,
                                       uint32_t& lo0, uint32_t& lo1) {
    __nv_bfloat162 h01 = __floats2bfloat162_rn(v.x, v.y);
    __nv_bfloat162 h23 = __floats2bfloat162_rn(v.z, v.w);
    __nv_bfloat162 l01 = __floats2bfloat162_rn(v.x - __bfloat162float(h01.x),
                                               v.y - __bfloat162float(h01.y));
    __nv_bfloat162 l23 = __floats2bfloat162_rn(v.z - __bfloat162float(h23.x),
                                               v.w - __bfloat162float(h23.y));
    memcpy(&hi0, &h01, 4); memcpy(&hi1, &h23, 4);
    memcpy(&lo0, &l01, 4); memcpy(&lo1, &l23, 4);
}

__global__ void split_x_kernel(const float* __restrict__ x,
                               __nv_bfloat16* __restrict__ xhi,
                               __nv_bfloat16* __restrict__ xlo, int n4) {
    int i = blockIdx.x * blockDim.x + threadIdx.x;
    if (i >= n4) return;
    float4 v = reinterpret_cast<const float4*>(x)[i];
    uint32_t h0, h1, l0, l1;
    split4(v, h0, h1, l0, l1);
    reinterpret_cast<uint2*>(xhi)[i] = make_uint2(h0, h1);
    reinterpret_cast<uint2*>(xlo)[i] = make_uint2(l0, l1);
}

__global__ void dequant_split_kernel(const float* __restrict__ cb,
                                     const int*   __restrict__ idx,
                                     __nv_bfloat16* __restrict__ Whi,
                                     __nv_bfloat16* __restrict__ Wlo,
                                     int rows, int sub) {
    const int per_row4 = (NCB * sub) >> 2;
    int tid = blockIdx.x * blockDim.x + threadIdx.x;
    if (tid >= rows * per_row4) return;
    int row = tid / per_row4;
    int col = (tid - row * per_row4) << 2;
    int c   = col / sub;
    int j   = col - c * sub;
    int code = __ldg(&idx[c * rows + row]);
    float4 v = *reinterpret_cast<const float4*>(cb + ((size_t)(c * KCB + code)) * sub + j);
    uint32_t h0, h1, l0, l1;
    split4(v, h0, h1, l0, l1);
    size_t off = (size_t)row * (NCB * sub) + col;
    *reinterpret_cast<uint2*>(Whi + off) = make_uint2(h0, h1);
    *reinterpret_cast<uint2*>(Wlo + off) = make_uint2(l0, l1);
}

// ---------------------------------------------------------------------------
// Pipelined bf16 mma.sync GEMM, 3-product hi/lo accumulation.
// CTA tile 128x128, BK=32, 3 stages, 128 threads (4 warps 2x2), warp 64x64.
// 2 CTAs/SM for cross-CTA stall overlap.
// Smem tile layout: [128 rows][32 k], row = 64 bytes, swizzled chunks:
//   addr(row, c16) = row*64 + ((c16 ^ ((row>>1)&3)) * 16)
// ---------------------------------------------------------------------------
#define BM 128
#define BN 128
#define BKE 32
#define STAGES 3
#define TILE_T  (BM * BKE * 2)                 // 8 KB per matrix tile
#define STAGE_B (4 * TILE_T)                   // 32 KB: Ahi, Alo, Bhi, Blo
#define SMEM_TOT (STAGES * STAGE_B)            // 96 KB

__device__ __forceinline__ void load_stage(uint32_t stage,
    const __nv_bfloat16* __restrict__ Ahi, const __nv_bfloat16* __restrict__ Alo,
    const __nv_bfloat16* __restrict__ Bhi, const __nv_bfloat16* __restrict__ Blo,
    int bm, int bn, int k0, int K, int tid)
{
    const int row = tid;                 // 0..127
    const uint32_t sx = ((uint32_t)(row >> 1)) & 3;
    const uint32_t rb = (uint32_t)row * 64;
    const __nv_bfloat16* pAh = Ahi + (size_t)(bm + row) * K + k0;
    const __nv_bfloat16* pAl = Alo + (size_t)(bm + row) * K + k0;
    const __nv_bfloat16* pBh = Bhi + (size_t)(bn + row) * K + k0;
    const __nv_bfloat16* pBl = Blo + (size_t)(bn + row) * K + k0;
    #pragma unroll
    for (int c = 0; c < 4; c++) {
        uint32_t d = stage + rb + (((uint32_t)c ^ sx) << 4);
        CP_ASYNC16(d + 0 * TILE_T, pAh + c * 8);
        CP_ASYNC16(d + 1 * TILE_T, pAl + c * 8);
        CP_ASYNC16(d + 2 * TILE_T, pBh + c * 8);
        CP_ASYNC16(d + 3 * TILE_T, pBl + c * 8);
    }
}

template<bool GELU, bool OUT_SPLIT>
__global__ __launch_bounds__(128, 2)
void gemm_bf3(const __nv_bfloat16* __restrict__ Ahi, const __nv_bfloat16* __restrict__ Alo,
              const __nv_bfloat16* __restrict__ Bhi, const __nv_bfloat16* __restrict__ Blo,
              const float* __restrict__ bias,
              float* __restrict__ Cf,
              __nv_bfloat16* __restrict__ Chi, __nv_bfloat16* __restrict__ Clo,
              int M, int N, int K)
{
    extern __shared__ __align__(1024) char smem[];
    const uint32_t sb = smem_u32(smem);
    const int tid  = threadIdx.x;
    const int wid  = tid >> 5;
    const int lane = tid & 31;
    const int wr   = wid & 1;          // warp m-tile (64 rows)
    const int wc   = wid >> 1;         // warp n-tile (64 cols)
    const int bm   = blockIdx.y * BM;
    const int bn   = blockIdx.x * BN;

    float acc[4][8][4];
    #pragma unroll
    for (int a = 0; a < 4; a++)
        #pragma unroll
        for (int b = 0; b < 8; b++)
            #pragma unroll
            for (int c = 0; c < 4; c++) acc[a][b][c] = 0.0f;

    // ldmatrix lane addressing (row width 64B, chunk-swizzled)
    const int amat = lane >> 3, ar = lane & 7;
    const int a_m  = wr * 64 + (amat & 1) * 8 + ar;        // + mt*16
    const uint32_t a_ck = (uint32_t)(amat >> 1);            // k 16B-chunk within k16 pair
    const uint32_t a_sx = ((uint32_t)(a_m >> 1)) & 3;       // invariant under +16
    const uint32_t a_rb = (uint32_t)a_m * 64;

    const int bmat = lane >> 3, br = lane & 7;
    const int b_n  = wc * 64 + ((bmat >> 1) << 3) + br;     // + pr*16
    const uint32_t b_ck = (uint32_t)(bmat & 1);
    const uint32_t b_sx = ((uint32_t)(b_n >> 1)) & 3;
    const uint32_t b_rb = (uint32_t)b_n * 64;

    const int NT = K / BKE;

    #pragma unroll
    for (int s = 0; s < STAGES - 1; s++) {
        load_stage(sb + s * STAGE_B, Ahi, Alo, Bhi, Blo, bm, bn, s * BKE, K, tid);
        CP_COMMIT();
    }

    for (int it = 0; it < NT; it++) {
        CP_WAIT1();
        __syncthreads();

        int pf = it + STAGES - 1;
        if (pf < NT)
            load_stage(sb + (pf % STAGES) * STAGE_B, Ahi, Alo, Bhi, Blo,
                       bm, bn, pf * BKE, K, tid);
        CP_COMMIT();   // always commit (possibly-empty group) to keep wait_group math exact

        const uint32_t st  = sb + (it % STAGES) * STAGE_B;
        const uint32_t sAh = st;
        const uint32_t sAl = st + TILE_T;
        const uint32_t sBh = st + 2 * TILE_T;
        const uint32_t sBl = st + 3 * TILE_T;

        #pragma unroll
        for (int kk = 0; kk < 2; kk++) {
            const uint32_t ckk = (uint32_t)kk * 2;
            uint32_t ahi[4][4], alo[4][4];
            #pragma unroll
            for (int mt = 0; mt < 4; mt++) {
                uint32_t off = a_rb + mt * 1024 + ((((ckk + a_ck) ^ a_sx)) << 4);
                LDSM_X4(ahi[mt][0], ahi[mt][1], ahi[mt][2], ahi[mt][3], sAh + off);
                LDSM_X4(alo[mt][0], alo[mt][1], alo[mt][2], alo[mt][3], sAl + off);
            }
            #pragma unroll
            for (int pr = 0; pr < 4; pr++) {
                uint32_t bhi[4], blo[4];
                uint32_t off = b_rb + pr * 1024 + ((((ckk + b_ck) ^ b_sx)) << 4);
                LDSM_X4(bhi[0], bhi[1], bhi[2], bhi[3], sBh + off);
                LDSM_X4(blo[0], blo[1], blo[2], blo[3], sBl + off);
                #pragma unroll
                for (int mt = 0; mt < 4; mt++) {
                    MMA_BF16(acc[mt][pr * 2 + 0], ahi[mt], bhi[0], bhi[1]);
                    MMA_BF16(acc[mt][pr * 2 + 1], ahi[mt], bhi[2], bhi[3]);
                }
                #pragma unroll
                for (int mt = 0; mt < 4; mt++) {
                    MMA_BF16(acc[mt][pr * 2 + 0], ahi[mt], blo[0], blo[1]);
                    MMA_BF16(acc[mt][pr * 2 + 1], ahi[mt], blo[2], blo[3]);
                }
                #pragma unroll
                for (int mt = 0; mt < 4; mt++) {
                    MMA_BF16(acc[mt][pr * 2 + 0], alo[mt], bhi[0], bhi[1]);
                    MMA_BF16(acc[mt][pr * 2 + 1], alo[mt], bhi[2], bhi[3]);
                }
            }
        }
    }

    // epilogue
    const int mrow = bm + wr * 64 + (lane >> 2);
    const int ncol = bn + wc * 64 + (lane & 3) * 2;
    #pragma unroll
    for (int mt = 0; mt < 4; mt++) {
        #pragma unroll
        for (int n8 = 0; n8 < 8; n8++) {
            const int n = ncol + n8 * 8;
            const float bs0 = __ldg(&bias[n]);
            const float bs1 = __ldg(&bias[n + 1]);
            #pragma unroll
            for (int hf = 0; hf < 2; hf++) {
                const int m = mrow + mt * 16 + hf * 8;
                float v0 = acc[mt][n8][hf * 2 + 0] + bs0;
                float v1 = acc[mt][n8][hf * 2 + 1] + bs1;
                if (GELU) {
                    v0 = 0.5f * v0 * (1.0f + erff(v0 * 0.70710678118654752440f));
                    v1 = 0.5f * v1 * (1.0f + erff(v1 * 0.70710678118654752440f));
                }
                if (OUT_SPLIT) {
                    __nv_bfloat162 h2 = __floats2bfloat162_rn(v0, v1);
                    __nv_bfloat162 l2 = __floats2bfloat162_rn(
                        v0 - __bfloat162float(h2.x), v1 - __bfloat162float(h2.y));
                    *reinterpret_cast<__nv_bfloat162*>(Chi + (size_t)m * N + n) = h2;
                    *reinterpret_cast<__nv_bfloat162*>(Clo + (size_t)m * N + n) = l2;
                } else {
                    *reinterpret_cast<float2*>(Cf + (size_t)m * N + n) = make_float2(v0, v1);
                }
            }
        }
    }
}

// ---------------------------------------------------------------------------
extern "C" void kernel_launch(void* const* d_in, const int* in_sizes, int n_in,
                              void* d_out, int out_size) {
    const float* x    = (const float*)d_in[0];
    const float* cb1  = (const float*)d_in[1];
    const int*   idx1 = (const int*)  d_in[2];
    const float* b1   = (const float*)d_in[3];
    const float* cb2  = (const float*)d_in[4];
    const int*   idx2 = (const int*)  d_in[5];
    const float* b2   = (const float*)d_in[6];
    float* out = (float*)d_out;

    __nv_bfloat16 *xhi, *xlo, *w1hi, *w1lo, *w2hi, *w2lo, *hhi, *hlo;
    cudaGetSymbolAddress((void**)&xhi,  g_xhi);
    cudaGetSymbolAddress((void**)&xlo,  g_xlo);
    cudaGetSymbolAddress((void**)&w1hi, g_w1hi);
    cudaGetSymbolAddress((void**)&w1lo, g_w1lo);
    cudaGetSymbolAddress((void**)&w2hi, g_w2hi);
    cudaGetSymbolAddress((void**)&w2lo, g_w2lo);
    cudaGetSymbolAddress((void**)&hhi,  g_hhi);
    cudaGetSymbolAddress((void**)&hlo,  g_hlo);

    cudaFuncSetAttribute(gemm_bf3<true, true>,
                         cudaFuncAttributeMaxDynamicSharedMemorySize, SMEM_TOT);
    cudaFuncSetAttribute(gemm_bf3<false, false>,
                         cudaFuncAttributeMaxDynamicSharedMemorySize, SMEM_TOT);

    {
        int n4 = (MTOK * DDIM) / 4;
        split_x_kernel<<<(n4 + 255) / 256, 256>>>(x, xhi, xlo, n4);
    }
    {
        int n4 = (HDIM * DDIM) / 4;
        dequant_split_kernel<<<(n4 + 255) / 256, 256>>>(cb1, idx1, w1hi, w1lo, HDIM, DDIM / NCB);
    }
    {
        int n4 = (DDIM * HDIM) / 4;
        dequant_split_kernel<<<(n4 + 255) / 256, 256>>>(cb2, idx2, w2hi, w2lo, DDIM, HDIM / NCB);
    }

    {
        dim3 grid(HDIM / BN, MTOK / BM);     // (32, 64)
        gemm_bf3<true, true><<<grid, 128, SMEM_TOT>>>(
            xhi, xlo, w1hi, w1lo, b1, nullptr, hhi, hlo, MTOK, HDIM, DDIM);
    }
    {
        dim3 grid(DDIM / BN, MTOK / BM);     // (8, 64)
        gemm_bf3<false, false><<<grid, 128, SMEM_TOT>>>(
            hhi, hlo, w2hi, w2lo, b2, out, nullptr, nullptr, MTOK, DDIM, HDIM);
    }
}

// round 8
// speedup vs baseline: 2.2735x; 2.2735x over previous
#include <cuda_runtime.h>
#include <cuda_bf16.h>
#include <math.h>
#include <stdint.h>

#define MTOK 8192
#define DDIM 1024
#define HDIM 4096
#define NCB  8
#define KCB  256

__device__ __nv_bfloat16 g_xhi [(size_t)MTOK * DDIM];
__device__ __nv_bfloat16 g_xlo [(size_t)MTOK * DDIM];
__device__ __nv_bfloat16 g_w1hi[(size_t)HDIM * DDIM];
__device__ __nv_bfloat16 g_w1lo[(size_t)HDIM * DDIM];
__device__ __nv_bfloat16 g_w2hi[(size_t)DDIM * HDIM];
__device__ __nv_bfloat16 g_w2lo[(size_t)DDIM * HDIM];
__device__ __nv_bfloat16 g_hhi [(size_t)MTOK * HDIM];
__device__ __nv_bfloat16 g_hlo [(size_t)MTOK * HDIM];

// ---------------------------------------------------------------------------
__device__ __forceinline__ uint32_t smem_u32(const void* p) {
    uint32_t a;
    asm("{ .reg .u64 t; cvta.to.shared.u64 t, %1; cvt.u32.u64 %0, t; }"
        : "=r"(a) : "l"(p));
    return a;
}

#define CP_ASYNC16(dst, src) \
    asm volatile("cp.async.cg.shared.global [%0], [%1], 16;" \
        :: "r"(dst), "l"(src) : "memory")
#define CP_COMMIT() asm volatile("cp.async.commit_group;" ::: "memory")
#define CP_WAIT0()  asm volatile("cp.async.wait_group 0;"  ::: "memory")

#define LDSM_X4(r0, r1, r2, r3, a) \
    asm volatile("ldmatrix.sync.aligned.m8n8.x4.shared.b16 {%0,%1,%2,%3}, [%4];" \
        : "=r"(r0), "=r"(r1), "=r"(r2), "=r"(r3) : "r"(a))

#define MMA_BF16(c, a, b0, b1) \
    asm volatile("mma.sync.aligned.m16n8k16.row.col.f32.bf16.bf16.f32 " \
        "{%0,%1,%2,%3}, {%4,%5,%6,%7}, {%8,%9}, {%0,%1,%2,%3};" \
        : "+f"((c)[0]), "+f"((c)[1]), "+f"((c)[2]), "+f"((c)[3]) \
        : "r"((a)[0]), "r"((a)[1]), "r"((a)[2]), "r"((a)[3]), "r"(b0), "r"(b1))

// ---------------------------------------------------------------------------
// Pre-pass kernels
// ---------------------------------------------------------------------------
__device__ __forceinline__ void split4(float4 v, uint32_t& hi0, uint32_t& hi1,
                                       uint32_t& lo0, uint32_t& lo1) {
    __nv_bfloat162 h01 = __floats2bfloat162_rn(v.x, v.y);
    __nv_bfloat162 h23 = __floats2bfloat162_rn(v.z, v.w);
    __nv_bfloat162 l01 = __floats2bfloat162_rn(v.x - __bfloat162float(h01.x),
                                               v.y - __bfloat162float(h01.y));
    __nv_bfloat162 l23 = __floats2bfloat162_rn(v.z - __bfloat162float(h23.x),
                                               v.w - __bfloat162float(h23.y));
    memcpy(&hi0, &h01, 4); memcpy(&hi1, &h23, 4);
    memcpy(&lo0, &l01, 4); memcpy(&lo1, &l23, 4);
}

__global__ void split_x_kernel(const float* __restrict__ x,
                               __nv_bfloat16* __restrict__ xhi,
                               __nv_bfloat16* __restrict__ xlo, int n4) {
    int i = blockIdx.x * blockDim.x + threadIdx.x;
    if (i >= n4) return;
    float4 v = reinterpret_cast<const float4*>(x)[i];
    uint32_t h0, h1, l0, l1;
    split4(v, h0, h1, l0, l1);
    reinterpret_cast<uint2*>(xhi)[i] = make_uint2(h0, h1);
    reinterpret_cast<uint2*>(xlo)[i] = make_uint2(l0, l1);
}

__global__ void dequant_split_kernel(const float* __restrict__ cb,
                                     const int*   __restrict__ idx,
                                     __nv_bfloat16* __restrict__ Whi,
                                     __nv_bfloat16* __restrict__ Wlo,
                                     int rows, int sub) {
    const int per_row4 = (NCB * sub) >> 2;
    int tid = blockIdx.x * blockDim.x + threadIdx.x;
    if (tid >= rows * per_row4) return;
    int row = tid / per_row4;
    int col = (tid - row * per_row4) << 2;
    int c   = col / sub;
    int j   = col - c * sub;
    int code = __ldg(&idx[c * rows + row]);
    float4 v = *reinterpret_cast<const float4*>(cb + ((size_t)(c * KCB + code)) * sub + j);
    uint32_t h0, h1, l0, l1;
    split4(v, h0, h1, l0, l1);
    size_t off = (size_t)row * (NCB * sub) + col;
    *reinterpret_cast<uint2*>(Whi + off) = make_uint2(h0, h1);
    *reinterpret_cast<uint2*>(Wlo + off) = make_uint2(l0, l1);
}

// ---------------------------------------------------------------------------
// Pipelined bf16 mma.sync GEMM, 3-product hi/lo accumulation.
// CTA tile 128x256, BK=64, 2-stage double buffer, 256 threads.
// 8 warps in 2(m) x 4(n); warp tile 64x64.
// Round-8: B-fragment prefetch pipeline + deferred gmem prefetch (kk==1).
// ---------------------------------------------------------------------------
#define BM 128
#define BN 256
#define BKE 64
#define TILE_A  (BM * BKE * 2)                 // 16 KB
#define TILE_BB (BN * BKE * 2)                 // 32 KB
#define STAGE_B (2 * TILE_A + 2 * TILE_BB)     // 96 KB
#define SMEM_TOT (2 * STAGE_B)                 // 192 KB

__device__ __forceinline__ void load_stage(uint32_t stage,
    const __nv_bfloat16* __restrict__ Ahi, const __nv_bfloat16* __restrict__ Alo,
    const __nv_bfloat16* __restrict__ Bhi, const __nv_bfloat16* __restrict__ Blo,
    int bm, int bn, int k0, int K, int tid)
{
    const int row = tid >> 1;            // 0..127
    const int kc0 = (tid & 1) * 4;       // 16B-chunk 0..7
    const uint32_t sw  = ((uint32_t)(row & 7)) << 4;
    const uint32_t rb  = (uint32_t)row * 128;
    const uint32_t sAh = stage;
    const uint32_t sAl = stage + TILE_A;
    const uint32_t sBh = stage + 2 * TILE_A;
    const uint32_t sBl = stage + 2 * TILE_A + TILE_BB;

    const __nv_bfloat16* pAh = Ahi + (size_t)(bm + row) * K + k0;
    const __nv_bfloat16* pAl = Alo + (size_t)(bm + row) * K + k0;
    #pragma unroll
    for (int i = 0; i < 4; i++) {
        int kc = kc0 + i;
        uint32_t d = rb + (((uint32_t)kc * 16) ^ sw);
        CP_ASYNC16(sAh + d, pAh + kc * 8);
        CP_ASYNC16(sAl + d, pAl + kc * 8);
    }
    #pragma unroll
    for (int g = 0; g < 2; g++) {
        int brow = row + g * 128;
        const __nv_bfloat16* pBh = Bhi + (size_t)(bn + brow) * K + k0;
        const __nv_bfloat16* pBl = Blo + (size_t)(bn + brow) * K + k0;
        uint32_t brb = (uint32_t)brow * 128;
        #pragma unroll
        for (int i = 0; i < 4; i++) {
            int kc = kc0 + i;
            uint32_t d = brb + (((uint32_t)kc * 16) ^ sw);
            CP_ASYNC16(sBh + d, pBh + kc * 8);
            CP_ASYNC16(sBl + d, pBl + kc * 8);
        }
    }
}

template<bool GELU, bool OUT_SPLIT>
__global__ __launch_bounds__(256, 1)
void gemm_bf3(const __nv_bfloat16* __restrict__ Ahi, const __nv_bfloat16* __restrict__ Alo,
              const __nv_bfloat16* __restrict__ Bhi, const __nv_bfloat16* __restrict__ Blo,
              const float* __restrict__ bias,
              float* __restrict__ Cf,
              __nv_bfloat16* __restrict__ Chi, __nv_bfloat16* __restrict__ Clo,
              int M, int N, int K)
{
    extern __shared__ __align__(1024) char smem[];
    const uint32_t sb = smem_u32(smem);
    const int tid  = threadIdx.x;
    const int wid  = tid >> 5;
    const int lane = tid & 31;
    const int wr   = wid & 1;          // warp m-tile (64 rows)
    const int wc   = wid >> 1;         // warp n-tile (64 cols)
    const int bm   = blockIdx.y * BM;
    const int bn   = blockIdx.x * BN;

    float acc[4][8][4];
    #pragma unroll
    for (int a = 0; a < 4; a++)
        #pragma unroll
        for (int b = 0; b < 8; b++)
            #pragma unroll
            for (int c = 0; c < 4; c++) acc[a][b][c] = 0.0f;

    // ldmatrix lane addressing
    const int amat = lane >> 3, ar = lane & 7;
    const int a_m  = wr * 64 + (amat & 1) * 8 + ar;      // + mt*16
    const uint32_t a_kh = (uint32_t)(amat >> 1) * 16;
    const uint32_t a_rb = (uint32_t)a_m * 128;
    const uint32_t a_sx = ((uint32_t)(a_m & 7)) << 4;

    const int bmat = lane >> 3, br = lane & 7;
    const int b_n  = wc * 64 + ((bmat >> 1) << 3) + br;  // + pr*16
    const uint32_t b_kh = (uint32_t)(bmat & 1) * 16;
    const uint32_t b_rb = (uint32_t)b_n * 128;
    const uint32_t b_sx = ((uint32_t)(b_n & 7)) << 4;

    const int NT = K / BKE;

    // prologue: prefetch stage 0
    load_stage(sb, Ahi, Alo, Bhi, Blo, bm, bn, 0, K, tid);
    CP_COMMIT();

    for (int it = 0; it < NT; it++) {
        CP_WAIT0();
        __syncthreads();

        const uint32_t st  = sb + (it & 1) * STAGE_B;
        const uint32_t sAh = st;
        const uint32_t sAl = st + TILE_A;
        const uint32_t sBh = st + 2 * TILE_A;
        const uint32_t sBl = st + 2 * TILE_A + TILE_BB;

        #pragma unroll
        for (int kk = 0; kk < 4; kk++) {
            // deferred gmem prefetch: after the first k16 block's work is issued
            if (kk == 1) {
                int pf = it + 1;
                if (pf < NT) {
                    load_stage(sb + (pf & 1) * STAGE_B, Ahi, Alo, Bhi, Blo,
                               bm, bn, pf * BKE, K, tid);
                    CP_COMMIT();
                }
            }

            const uint32_t kb = (uint32_t)kk * 32;
            uint32_t ahi[4][4], alo[4][4];
            #pragma unroll
            for (int mt = 0; mt < 4; mt++) {
                uint32_t off = a_rb + mt * 2048 + ((kb + a_kh) ^ a_sx);
                LDSM_X4(ahi[mt][0], ahi[mt][1], ahi[mt][2], ahi[mt][3], sAh + off);
                LDSM_X4(alo[mt][0], alo[mt][1], alo[mt][2], alo[mt][3], sAl + off);
            }

            // B-fragment double buffer across pr
            uint32_t bh[2][4], bl[2][4];
            {
                uint32_t off0 = b_rb + ((kb + b_kh) ^ b_sx);
                LDSM_X4(bh[0][0], bh[0][1], bh[0][2], bh[0][3], sBh + off0);
                LDSM_X4(bl[0][0], bl[0][1], bl[0][2], bl[0][3], sBl + off0);
            }
            #pragma unroll
            for (int pr = 0; pr < 4; pr++) {
                const int cur = pr & 1;
                const int nxt = cur ^ 1;
                if (pr < 3) {
                    uint32_t offn = b_rb + (pr + 1) * 2048 + ((kb + b_kh) ^ b_sx);
                    LDSM_X4(bh[nxt][0], bh[nxt][1], bh[nxt][2], bh[nxt][3], sBh + offn);
                    LDSM_X4(bl[nxt][0], bl[nxt][1], bl[nxt][2], bl[nxt][3], sBl + offn);
                }
                #pragma unroll
                for (int mt = 0; mt < 4; mt++) {
                    MMA_BF16(acc[mt][pr * 2 + 0], ahi[mt], bh[cur][0], bh[cur][1]);
                    MMA_BF16(acc[mt][pr * 2 + 1], ahi[mt], bh[cur][2], bh[cur][3]);
                }
                #pragma unroll
                for (int mt = 0; mt < 4; mt++) {
                    MMA_BF16(acc[mt][pr * 2 + 0], ahi[mt], bl[cur][0], bl[cur][1]);
                    MMA_BF16(acc[mt][pr * 2 + 1], ahi[mt], bl[cur][2], bl[cur][3]);
                }
                #pragma unroll
                for (int mt = 0; mt < 4; mt++) {
                    MMA_BF16(acc[mt][pr * 2 + 0], alo[mt], bh[cur][0], bh[cur][1]);
                    MMA_BF16(acc[mt][pr * 2 + 1], alo[mt], bh[cur][2], bh[cur][3]);
                }
            }
        }
    }

    // epilogue
    const int mrow = bm + wr * 64 + (lane >> 2);
    const int ncol = bn + wc * 64 + (lane & 3) * 2;
    #pragma unroll
    for (int mt = 0; mt < 4; mt++) {
        #pragma unroll
        for (int n8 = 0; n8 < 8; n8++) {
            const int n = ncol + n8 * 8;
            const float bs0 = __ldg(&bias[n]);
            const float bs1 = __ldg(&bias[n + 1]);
            #pragma unroll
            for (int hf = 0; hf < 2; hf++) {
                const int m = mrow + mt * 16 + hf * 8;
                float v0 = acc[mt][n8][hf * 2 + 0] + bs0;
                float v1 = acc[mt][n8][hf * 2 + 1] + bs1;
                if (GELU) {
                    v0 = 0.5f * v0 * (1.0f + erff(v0 * 0.70710678118654752440f));
                    v1 = 0.5f * v1 * (1.0f + erff(v1 * 0.70710678118654752440f));
                }
                if (OUT_SPLIT) {
                    __nv_bfloat162 h2 = __floats2bfloat162_rn(v0, v1);
                    __nv_bfloat162 l2 = __floats2bfloat162_rn(
                        v0 - __bfloat162float(h2.x), v1 - __bfloat162float(h2.y));
                    *reinterpret_cast<__nv_bfloat162*>(Chi + (size_t)m * N + n) = h2;
                    *reinterpret_cast<__nv_bfloat162*>(Clo + (size_t)m * N + n) = l2;
                } else {
                    *reinterpret_cast<float2*>(Cf + (size_t)m * N + n) = make_float2(v0, v1);
                }
            }
        }
    }
}

// ---------------------------------------------------------------------------
extern "C" void kernel_launch(void* const* d_in, const int* in_sizes, int n_in,
                              void* d_out, int out_size) {
    const float* x    = (const float*)d_in[0];
    const float* cb1  = (const float*)d_in[1];
    const int*   idx1 = (const int*)  d_in[2];
    const float* b1   = (const float*)d_in[3];
    const float* cb2  = (const float*)d_in[4];
    const int*   idx2 = (const int*)  d_in[5];
    const float* b2   = (const float*)d_in[6];
    float* out = (float*)d_out;

    __nv_bfloat16 *xhi, *xlo, *w1hi, *w1lo, *w2hi, *w2lo, *hhi, *hlo;
    cudaGetSymbolAddress((void**)&xhi,  g_xhi);
    cudaGetSymbolAddress((void**)&xlo,  g_xlo);
    cudaGetSymbolAddress((void**)&w1hi, g_w1hi);
    cudaGetSymbolAddress((void**)&w1lo, g_w1lo);
    cudaGetSymbolAddress((void**)&w2hi, g_w2hi);
    cudaGetSymbolAddress((void**)&w2lo, g_w2lo);
    cudaGetSymbolAddress((void**)&hhi,  g_hhi);
    cudaGetSymbolAddress((void**)&hlo,  g_hlo);

    cudaFuncSetAttribute(gemm_bf3<true, true>,
                         cudaFuncAttributeMaxDynamicSharedMemorySize, SMEM_TOT);
    cudaFuncSetAttribute(gemm_bf3<false, false>,
                         cudaFuncAttributeMaxDynamicSharedMemorySize, SMEM_TOT);

    {
        int n4 = (MTOK * DDIM) / 4;
        split_x_kernel<<<(n4 + 255) / 256, 256>>>(x, xhi, xlo, n4);
    }
    {
        int n4 = (HDIM * DDIM) / 4;
        dequant_split_kernel<<<(n4 + 255) / 256, 256>>>(cb1, idx1, w1hi, w1lo, HDIM, DDIM / NCB);
    }
    {
        int n4 = (DDIM * HDIM) / 4;
        dequant_split_kernel<<<(n4 + 255) / 256, 256>>>(cb2, idx2, w2hi, w2lo, DDIM, HDIM / NCB);
    }

    {
        dim3 grid(HDIM / BN, MTOK / BM);     // (16, 64)
        gemm_bf3<true, true><<<grid, 256, SMEM_TOT>>>(
            xhi, xlo, w1hi, w1lo, b1, nullptr, hhi, hlo, MTOK, HDIM, DDIM);
    }
    {
        dim3 grid(DDIM / BN, MTOK / BM);     // (4, 64)
        gemm_bf3<false, false><<<grid, 256, SMEM_TOT>>>(
            hhi, hlo, w2hi, w2lo, b2, out, nullptr, nullptr, MTOK, DDIM, HDIM);
    }
}